// round 16
// baseline (speedup 1.0000x reference)
#include <cuda_runtime.h>
#include <cuda_fp16.h>
#include <math.h>
#include <stdint.h>

#define T_TOK 4096
#define DM 1024
#define DF 4096
#define NE 8
#define NP 8192   // T_TOK * TOP_K

#define BM 128
#define BN 256
#define BK 64
#define NST 3
#define STAGE_BYTES 49152      // A: 128*128B = 16KB, B: 64*512B = 32KB
#define B_OFF 16384
#define SMEM_DYN (NST * STAGE_BYTES)   // 144 KB

#define N4_W1 (NE * DM * DF / 4)
#define N4_W2 (NE * DF * DM / 4)
#define N4_X  (T_TOK * DM / 4)

// ---------------- scratch (device globals; no runtime allocations) ----------
__device__ int    g_off[NE + 1];
__device__ int    g_tok_e[NP];
__device__ float  g_tok_w[NP];
__device__ int    g_slot_tok[NP];   // sorted slot -> token
__device__ float  g_slot_w[NP];     // sorted slot -> gate weight
__device__ __half g_w1h[(size_t)NE * DM * DF];   // 67 MB
__device__ __half g_w2h[(size_t)NE * DF * DM];   // 67 MB
__device__ __half g_xh[(size_t)T_TOK * DM];      // 8 MB
__device__ __half g_h[(size_t)NP * DF];          // 67 MB hidden acts (fp16)

// ---------------- PTX helpers ------------------------------------------------
__device__ __forceinline__ uint32_t smem_u32(const void* p) {
    uint32_t a;
    asm("{ .reg .u64 t; cvta.to.shared.u64 t, %1; cvt.u32.u64 %0, t; }"
        : "=r"(a) : "l"(p));
    return a;
}

__device__ __forceinline__ void cp16(uint32_t s, const void* g) {
    asm volatile("cp.async.cg.shared.global [%0], [%1], 16;"
                 :: "r"(s), "l"(g) : "memory");
}
#define CP_COMMIT() asm volatile("cp.async.commit_group;" ::: "memory")
#define CP_WAIT1()  asm volatile("cp.async.wait_group 1;" ::: "memory")

__device__ __forceinline__ void ldsm_x4(uint32_t* r, uint32_t addr) {
    asm volatile("ldmatrix.sync.aligned.m8n8.x4.shared.b16 {%0,%1,%2,%3}, [%4];"
                 : "=r"(r[0]), "=r"(r[1]), "=r"(r[2]), "=r"(r[3]) : "r"(addr));
}
__device__ __forceinline__ void ldsm_x4_t(uint32_t* r, uint32_t addr) {
    asm volatile("ldmatrix.sync.aligned.m8n8.x4.trans.shared.b16 {%0,%1,%2,%3}, [%4];"
                 : "=r"(r[0]), "=r"(r[1]), "=r"(r[2]), "=r"(r[3]) : "r"(addr));
}
__device__ __forceinline__ void mma_16816(float* c, const uint32_t* a,
                                          const uint32_t* b) {
    asm volatile(
        "mma.sync.aligned.m16n8k16.row.col.f32.f16.f16.f32 "
        "{%0,%1,%2,%3},{%4,%5,%6,%7},{%8,%9},{%0,%1,%2,%3};"
        : "+f"(c[0]), "+f"(c[1]), "+f"(c[2]), "+f"(c[3])
        : "r"(a[0]), "r"(a[1]), "r"(a[2]), "r"(a[3]), "r"(b[0]), "r"(b[1]));
}

// ---------------- zero the (poisoned) output ---------------------------------
__global__ void zero_out_kernel(float4* __restrict__ out) {
    int i = blockIdx.x * blockDim.x + threadIdx.x;
    out[i] = make_float4(0.f, 0.f, 0.f, 0.f);
}

// ---------------- gating: one warp per token ---------------------------------
__global__ void gate_kernel(const float* __restrict__ x,
                            const float* __restrict__ Wg,
                            const float* __restrict__ bg) {
    int warp = threadIdx.x >> 5, lane = threadIdx.x & 31;
    int t = blockIdx.x * 4 + warp;
    const float* xr = x + (size_t)t * DM;

    float acc[NE];
#pragma unroll
    for (int e = 0; e < NE; e++) acc[e] = 0.f;

    for (int d = lane; d < DM; d += 32) {
        float xv = xr[d];
        const float* wr = Wg + d * NE;
#pragma unroll
        for (int e = 0; e < NE; e++) acc[e] = fmaf(xv, wr[e], acc[e]);
    }
#pragma unroll
    for (int e = 0; e < NE; e++)
#pragma unroll
        for (int o = 16; o > 0; o >>= 1)
            acc[e] += __shfl_xor_sync(0xffffffffu, acc[e], o);

    if (lane == 0) {
        float v[NE];
#pragma unroll
        for (int e = 0; e < NE; e++) v[e] = acc[e] + bg[e];
        int i0 = 0;
        for (int e = 1; e < NE; e++) if (v[e] > v[i0]) i0 = e;
        int i1 = (i0 == 0) ? 1 : 0;
        for (int e = 0; e < NE; e++) { if (e == i0) continue; if (v[e] > v[i1]) i1 = e; }
        float e1 = expf(v[i1] - v[i0]);
        float s  = 1.f + e1;
        g_tok_e[2 * t]     = i0;  g_tok_w[2 * t]     = 1.f / s;
        g_tok_e[2 * t + 1] = i1;  g_tok_w[2 * t + 1] = e1 / s;
    }
}

// ---------------- route: single block, count + prefix + scatter --------------
__global__ void route_kernel() {
    __shared__ int cnt[NE], cur[NE];
    int tid = threadIdx.x;
    if (tid < NE) cnt[tid] = 0;
    __syncthreads();
    for (int p = tid; p < NP; p += blockDim.x)
        atomicAdd(&cnt[g_tok_e[p]], 1);
    __syncthreads();
    if (tid == 0) {
        int acc = 0;
        for (int e = 0; e < NE; e++) {
            g_off[e] = acc;
            cur[e] = acc;
            acc += cnt[e];
        }
        g_off[NE] = acc;
    }
    __syncthreads();
    for (int p = tid; p < NP; p += blockDim.x) {
        int slot = atomicAdd(&cur[g_tok_e[p]], 1);
        g_slot_tok[slot] = p >> 1;
        g_slot_w[slot]   = g_tok_w[p];
    }
}

// ---------------- fp32 -> fp16 converts (ILP 2) ------------------------------
__global__ void cvt_w1x_kernel(const float* __restrict__ W1,
                               const float* __restrict__ x) {
    int base = blockIdx.x * (blockDim.x * 2) + threadIdx.x;
#pragma unroll
    for (int u = 0; u < 2; u++) {
        int i = base + u * blockDim.x;
        if (i >= N4_W1 + N4_X) continue;
        const float* src;
        __half* dst;
        int j;
        if (i < N4_W1) { src = W1; dst = g_w1h; j = i; }
        else           { src = x;  dst = g_xh;  j = i - N4_W1; }
        float4 v = ((const float4*)src)[j];
        ((__half2*)dst)[2 * j]     = __floats2half2_rn(v.x, v.y);
        ((__half2*)dst)[2 * j + 1] = __floats2half2_rn(v.z, v.w);
    }
}

__global__ void cvt_w2_kernel(const float* __restrict__ W2) {
    int base = blockIdx.x * (blockDim.x * 2) + threadIdx.x;
#pragma unroll
    for (int u = 0; u < 2; u++) {
        int i = base + u * blockDim.x;
        if (i >= N4_W2) continue;
        float4 v = ((const float4*)W2)[i];
        ((__half2*)g_w2h)[2 * i]     = __floats2half2_rn(v.x, v.y);
        ((__half2*)g_w2h)[2 * i + 1] = __floats2half2_rn(v.z, v.w);
    }
}

// ---------------- fp16 tensor GEMM (R11 core; fused atomic combine in G2) ----
// CTA tile 128x256, BK=64, NST=3. 256 threads, 8 warps (2 M x 4 N),
// warp tile 64x64, ks-level fragment double buffering.
// G1: h = relu(x@W1 + b1) -> g_h (fp16).
// G2: per-row gate weight w = g_slot_w[slot]; epilogue does
//     atomicAdd(out + token*DM + col, w*(acc + b2)).  Each (token, col)
//     receives exactly two contributions (top-2) onto a zeroed buffer, and
//     fp32 a+b is commutative -> result is order-independent (deterministic).
// A smem: [128 rows][64 halfs] (128B row, 8 chunks), phys chunk = c ^ (row&7)
// B smem: [64 k-rows][256 halfs] (512B row, 32 chunks), phys chunk = c ^ (k&7)
template <int KDIM, int OUTD, bool G1>
__global__ void __launch_bounds__(256, 1)
gemm_h(const float* __restrict__ bias, float* __restrict__ out) {
    extern __shared__ char smraw[];
    uint32_t sb = smem_u32(smraw);
    int tid = threadIdx.x, lane = tid & 31, wid = tid >> 5;
    int e = blockIdx.z;
    int off = g_off[e], cnt = g_off[e + 1] - off;
    int m0 = blockIdx.y * BM;
    if (m0 >= cnt) return;
    int n0 = blockIdx.x * BN;
    const __half* W = (G1 ? g_w1h : g_w2h) + (size_t)e * KDIM * OUTD;
    const float* be = bias + (size_t)e * OUTD;

    int arow = tid & 127;
    int ac   = tid >> 7;
    int amr  = m0 + arow; if (amr >= cnt) amr = cnt - 1;
    const __half* aptr;
    if (G1) aptr = g_xh + (size_t)g_slot_tok[off + amr] * KDIM;
    else    aptr = g_h  + (size_t)(off + amr) * KDIM;
    uint32_t a_dst[4];
    int a_go[4];
#pragma unroll
    for (int i = 0; i < 4; i++) {
        int c = ac + 2 * i;
        a_dst[i] = sb + arow * 128 + ((uint32_t)(c ^ (arow & 7))) * 16;
        a_go[i]  = c * 8;
    }

    int bk = tid >> 2;
    int blo = tid & 3;
    const __half* bptr = W + (size_t)bk * OUTD + n0;
    uint32_t b_dst[8];
    int b_go[8];
#pragma unroll
    for (int j = 0; j < 8; j++) {
        int c = blo + 4 * j;
        b_dst[j] = sb + B_OFF + bk * 512 + ((uint32_t)(c ^ (bk & 7))) * 16;
        b_go[j]  = c * 8;
    }

    int warpM = wid & 1, warpN = wid >> 1;
    uint32_t aFb = sb + (warpM * 64 + (lane & 15)) * 128;
    int hi = lane >> 4;
    uint32_t bFb = sb + B_OFF + (lane & 15) * 512;
    uint32_t swz = lane & 7;

    float acc[4][8][4];
#pragma unroll
    for (int mi = 0; mi < 4; mi++)
#pragma unroll
        for (int ni = 0; ni < 8; ni++)
#pragma unroll
            for (int q = 0; q < 4; q++) acc[mi][ni][q] = 0.f;

    const int NC = KDIM / BK;

#pragma unroll
    for (int s = 0; s < NST - 1; s++) {
        uint32_t so = s * STAGE_BYTES;
        const __half* ap = aptr + (size_t)s * BK;
        const __half* bp = bptr + (size_t)s * BK * OUTD;
#pragma unroll
        for (int i = 0; i < 4; i++) cp16(a_dst[i] + so, ap + a_go[i]);
#pragma unroll
        for (int j = 0; j < 8; j++) cp16(b_dst[j] + so, bp + b_go[j]);
        CP_COMMIT();
    }

    uint32_t afr[2][4][4], bfr[2][4][4];

    for (int c = 0; c < NC; c++) {
        CP_WAIT1();
        __syncthreads();

        int nc = c + NST - 1;
        if (nc < NC) {
            uint32_t so = (nc % NST) * STAGE_BYTES;
            const __half* ap = aptr + (size_t)nc * BK;
            const __half* bp = bptr + (size_t)nc * BK * OUTD;
#pragma unroll
            for (int i = 0; i < 4; i++) cp16(a_dst[i] + so, ap + a_go[i]);
#pragma unroll
            for (int j = 0; j < 8; j++) cp16(b_dst[j] + so, bp + b_go[j]);
        }
        CP_COMMIT();

        uint32_t so = (c % NST) * STAGE_BYTES;

#pragma unroll
        for (int mi = 0; mi < 4; mi++)
            ldsm_x4(afr[0][mi], aFb + so + mi * 2048 +
                    ((uint32_t)((0 * 2 + hi) ^ swz)) * 16);
#pragma unroll
        for (int p = 0; p < 4; p++)
            ldsm_x4_t(bfr[0][p], bFb + so + 0 * 8192 +
                      ((uint32_t)((warpN * 8 + p * 2 + hi) ^ swz)) * 16);

#pragma unroll
        for (int ks = 0; ks < 4; ks++) {
            int cur = ks & 1, nxt = cur ^ 1;
            if (ks < 3) {
#pragma unroll
                for (int mi = 0; mi < 4; mi++)
                    ldsm_x4(afr[nxt][mi], aFb + so + mi * 2048 +
                            ((uint32_t)(((ks + 1) * 2 + hi) ^ swz)) * 16);
#pragma unroll
                for (int p = 0; p < 4; p++)
                    ldsm_x4_t(bfr[nxt][p], bFb + so + (ks + 1) * 8192 +
                              ((uint32_t)((warpN * 8 + p * 2 + hi) ^ swz)) * 16);
            }
#pragma unroll
            for (int mi = 0; mi < 4; mi++)
#pragma unroll
                for (int ni = 0; ni < 8; ni++)
                    mma_16816(acc[mi][ni], afr[cur][mi],
                              &bfr[cur][ni >> 1][(ni & 1) * 2]);
        }
    }

    int gid = lane >> 2, tig = lane & 3;
#pragma unroll
    for (int mi = 0; mi < 4; mi++) {
#pragma unroll
        for (int h2 = 0; h2 < 2; h2++) {
            int mrel = m0 + warpM * 64 + mi * 16 + gid + h2 * 8;
            if (mrel >= cnt) continue;
            int slot = off + mrel;
            if (G1) {
                size_t rowbase = (size_t)slot * OUTD;
#pragma unroll
                for (int ni = 0; ni < 8; ni++) {
                    int col = n0 + warpN * 64 + ni * 8 + 2 * tig;
                    float v0 = fmaxf(acc[mi][ni][h2 * 2 + 0] + be[col], 0.f);
                    float v1 = fmaxf(acc[mi][ni][h2 * 2 + 1] + be[col + 1], 0.f);
                    *(__half2*)(g_h + rowbase + col) = __floats2half2_rn(v0, v1);
                }
            } else {
                int token = g_slot_tok[slot];
                float w   = g_slot_w[slot];
                float* orow = out + (size_t)token * OUTD;
#pragma unroll
                for (int ni = 0; ni < 8; ni++) {
                    int col = n0 + warpN * 64 + ni * 8 + 2 * tig;
                    float v0 = w * (acc[mi][ni][h2 * 2 + 0] + be[col]);
                    float v1 = w * (acc[mi][ni][h2 * 2 + 1] + be[col + 1]);
                    atomicAdd(orow + col, v0);
                    atomicAdd(orow + col + 1, v1);
                }
            }
        }
    }
}

// -----------------------------------------------------------------------------
static cudaStream_t g_s1 = nullptr;
static cudaEvent_t  g_e0 = nullptr, g_e1 = nullptr, g_e2 = nullptr;

extern "C" void kernel_launch(void* const* d_in, const int* in_sizes, int n_in,
                              void* d_out, int out_size) {
    const float* x  = (const float*)d_in[0];
    const float* Wg = (const float*)d_in[1];
    const float* bg = (const float*)d_in[2];
    const float* W1 = (const float*)d_in[3];
    const float* b1 = (const float*)d_in[4];
    const float* W2 = (const float*)d_in[5];
    const float* b2 = (const float*)d_in[6];
    float* out = (float*)d_out;

    if (!g_s1) {
        cudaStreamCreateWithFlags(&g_s1, cudaStreamNonBlocking);
        cudaEventCreateWithFlags(&g_e0, cudaEventDisableTiming);
        cudaEventCreateWithFlags(&g_e1, cudaEventDisableTiming);
        cudaEventCreateWithFlags(&g_e2, cudaEventDisableTiming);
        cudaFuncSetAttribute(gemm_h<DM, DF, true>,
                             cudaFuncAttributeMaxDynamicSharedMemorySize, SMEM_DYN);
        cudaFuncSetAttribute(gemm_h<DF, DM, false>,
                             cudaFuncAttributeMaxDynamicSharedMemorySize, SMEM_DYN);
    }

    // fork side stream for weight conversion
    cudaEventRecord(g_e0, 0);
    cudaStreamWaitEvent(g_s1, g_e0, 0);
    cvt_w1x_kernel<<<(N4_W1 + N4_X + 511) / 512, 256, 0, g_s1>>>(W1, x);
    cudaEventRecord(g_e1, g_s1);
    cvt_w2_kernel<<<(N4_W2 + 511) / 512, 256, 0, g_s1>>>(W2);
    cudaEventRecord(g_e2, g_s1);

    // main stream: zero output + routing in parallel with converts
    zero_out_kernel<<<(T_TOK * DM / 4) / 256, 256>>>((float4*)out);
    gate_kernel<<<T_TOK / 4, 128>>>(x, Wg, bg);
    route_kernel<<<1, 1024>>>();

    cudaStreamWaitEvent(0, g_e1, 0);   // need W1 + x halves
    gemm_h<DM, DF, true><<<dim3(DF / BN, T_TOK / BM, NE), 256, SMEM_DYN>>>(b1, out);
    cudaStreamWaitEvent(0, g_e2, 0);   // need W2 half (joins side stream)
    gemm_h<DF, DM, false><<<dim3(DM / BN, T_TOK / BM, NE), 256, SMEM_DYN>>>(b2, out);
}

// round 17
// speedup vs baseline: 1.0668x; 1.0668x over previous
#include <cuda_runtime.h>
#include <cuda_fp16.h>
#include <math.h>
#include <stdint.h>

#define T_TOK 4096
#define DM 1024
#define DF 4096
#define NE 8
#define NP 8192   // T_TOK * TOP_K

#define BM 128
#define BN 256
#define BK 64
#define NST 3
#define STAGE_BYTES 49152      // A: 128*128B = 16KB, B: 64*512B = 32KB
#define B_OFF 16384
#define SMEM_DYN (NST * STAGE_BYTES)   // 144 KB

#define N4_W1 (NE * DM * DF / 4)
#define N4_W2 (NE * DF * DM / 4)
#define N4_X  (T_TOK * DM / 4)

// ---------------- scratch (device globals; no runtime allocations) ----------
__device__ int    g_off[NE + 1];
__device__ int    g_tok_e[NP];
__device__ float  g_tok_w[NP];
__device__ int    g_slot_tok[NP];
__device__ int    g_tok_slot[NP];
__device__ __half g_w1h[(size_t)NE * DM * DF];   // 67 MB
__device__ __half g_w2h[(size_t)NE * DF * DM];   // 67 MB
__device__ __half g_xh[(size_t)T_TOK * DM];      // 8 MB
__device__ __half g_h[(size_t)NP * DF];          // 67 MB hidden acts (fp16)
__device__ float  g_y[(size_t)NP * DM];          // 32 MB per-pair outputs

// ---------------- PTX helpers ------------------------------------------------
__device__ __forceinline__ uint32_t smem_u32(const void* p) {
    uint32_t a;
    asm("{ .reg .u64 t; cvta.to.shared.u64 t, %1; cvt.u32.u64 %0, t; }"
        : "=r"(a) : "l"(p));
    return a;
}

__device__ __forceinline__ void cp16(uint32_t s, const void* g) {
    asm volatile("cp.async.cg.shared.global [%0], [%1], 16;"
                 :: "r"(s), "l"(g) : "memory");
}
#define CP_COMMIT() asm volatile("cp.async.commit_group;" ::: "memory")
#define CP_WAIT1()  asm volatile("cp.async.wait_group 1;" ::: "memory")

__device__ __forceinline__ void ldsm_x4(uint32_t* r, uint32_t addr) {
    asm volatile("ldmatrix.sync.aligned.m8n8.x4.shared.b16 {%0,%1,%2,%3}, [%4];"
                 : "=r"(r[0]), "=r"(r[1]), "=r"(r[2]), "=r"(r[3]) : "r"(addr));
}
__device__ __forceinline__ void ldsm_x4_t(uint32_t* r, uint32_t addr) {
    asm volatile("ldmatrix.sync.aligned.m8n8.x4.trans.shared.b16 {%0,%1,%2,%3}, [%4];"
                 : "=r"(r[0]), "=r"(r[1]), "=r"(r[2]), "=r"(r[3]) : "r"(addr));
}
__device__ __forceinline__ void mma_16816(float* c, const uint32_t* a,
                                          const uint32_t* b) {
    asm volatile(
        "mma.sync.aligned.m16n8k16.row.col.f32.f16.f16.f32 "
        "{%0,%1,%2,%3},{%4,%5,%6,%7},{%8,%9},{%0,%1,%2,%3};"
        : "+f"(c[0]), "+f"(c[1]), "+f"(c[2]), "+f"(c[3])
        : "r"(a[0]), "r"(a[1]), "r"(a[2]), "r"(a[3]), "r"(b[0]), "r"(b[1]));
}

// ---------------- gating v2: smem-staged transposed Wg -----------------------
// 128 threads/block, 16 tokens/block (warp-per-token, 4 passes).
// wgT[e][d] staged once (32 KB); all inner loads are conflict-free float4.
__global__ void gate_kernel(const float* __restrict__ x,
                            const float* __restrict__ Wg,
                            const float* __restrict__ bg) {
    __shared__ float wgT[NE][DM];   // 32 KB
    int tid = threadIdx.x;
    // load + transpose Wg (row-major [d][e]) -> wgT[e][d]
    for (int i = tid; i < DM * NE; i += 128) {
        int d = i >> 3, e = i & 7;
        wgT[e][d] = Wg[i];
    }
    __syncthreads();

    int warp = tid >> 5, lane = tid & 31;
#pragma unroll
    for (int tt = 0; tt < 4; tt++) {
        int t = blockIdx.x * 16 + tt * 4 + warp;
        const float* xr = x + (size_t)t * DM;

        float acc[NE];
#pragma unroll
        for (int e = 0; e < NE; e++) acc[e] = 0.f;

#pragma unroll
        for (int i = 0; i < DM / 128; i++) {
            int d = lane * 4 + i * 128;
            float4 xv = *(const float4*)(xr + d);
#pragma unroll
            for (int e = 0; e < NE; e++) {
                float4 wv = *(const float4*)(&wgT[e][d]);
                acc[e] += xv.x * wv.x + xv.y * wv.y + xv.z * wv.z + xv.w * wv.w;
            }
        }
#pragma unroll
        for (int e = 0; e < NE; e++)
#pragma unroll
            for (int o = 16; o > 0; o >>= 1)
                acc[e] += __shfl_xor_sync(0xffffffffu, acc[e], o);

        if (lane == 0) {
            float v[NE];
#pragma unroll
            for (int e = 0; e < NE; e++) v[e] = acc[e] + bg[e];
            int i0 = 0;
            for (int e = 1; e < NE; e++) if (v[e] > v[i0]) i0 = e;
            int i1 = (i0 == 0) ? 1 : 0;
            for (int e = 0; e < NE; e++) {
                if (e == i0) continue;
                if (v[e] > v[i1]) i1 = e;
            }
            float e1 = expf(v[i1] - v[i0]);
            float s  = 1.f + e1;
            g_tok_e[2 * t]     = i0;  g_tok_w[2 * t]     = 1.f / s;
            g_tok_e[2 * t + 1] = i1;  g_tok_w[2 * t + 1] = e1 / s;
        }
    }
}

// ---------------- route: single block, count + prefix + scatter --------------
__global__ void route_kernel() {
    __shared__ int cnt[NE], cur[NE];
    int tid = threadIdx.x;
    if (tid < NE) cnt[tid] = 0;
    __syncthreads();
    for (int p = tid; p < NP; p += blockDim.x)
        atomicAdd(&cnt[g_tok_e[p]], 1);
    __syncthreads();
    if (tid == 0) {
        int acc = 0;
        for (int e = 0; e < NE; e++) {
            g_off[e] = acc;
            cur[e] = acc;
            acc += cnt[e];
        }
        g_off[NE] = acc;
    }
    __syncthreads();
    for (int p = tid; p < NP; p += blockDim.x) {
        int slot = atomicAdd(&cur[g_tok_e[p]], 1);
        g_slot_tok[slot] = p >> 1;
        g_tok_slot[p] = slot;
    }
}

// ---------------- fp32 -> fp16 converts (ILP 2) ------------------------------
__global__ void cvt_w1x_kernel(const float* __restrict__ W1,
                               const float* __restrict__ x) {
    int base = blockIdx.x * (blockDim.x * 2) + threadIdx.x;
#pragma unroll
    for (int u = 0; u < 2; u++) {
        int i = base + u * blockDim.x;
        if (i >= N4_W1 + N4_X) continue;
        const float* src;
        __half* dst;
        int j;
        if (i < N4_W1) { src = W1; dst = g_w1h; j = i; }
        else           { src = x;  dst = g_xh;  j = i - N4_W1; }
        float4 v = ((const float4*)src)[j];
        ((__half2*)dst)[2 * j]     = __floats2half2_rn(v.x, v.y);
        ((__half2*)dst)[2 * j + 1] = __floats2half2_rn(v.z, v.w);
    }
}

__global__ void cvt_w2_kernel(const float* __restrict__ W2) {
    int base = blockIdx.x * (blockDim.x * 2) + threadIdx.x;
#pragma unroll
    for (int u = 0; u < 2; u++) {
        int i = base + u * blockDim.x;
        if (i >= N4_W2) continue;
        float4 v = ((const float4*)W2)[i];
        ((__half2*)g_w2h)[2 * i]     = __floats2half2_rn(v.x, v.y);
        ((__half2*)g_w2h)[2 * i + 1] = __floats2half2_rn(v.z, v.w);
    }
}

// ---------------- fp16 tensor GEMM (R11 core, unchanged) ---------------------
// CTA tile 128x256, BK=64, NST=3. 256 threads, 8 warps (2 M x 4 N),
// warp tile 64x64, ks-level fragment double buffering.
// A smem: [128 rows][64 halfs] (128B row, 8 chunks), phys chunk = c ^ (row&7)
// B smem: [64 k-rows][256 halfs] (512B row, 32 chunks), phys chunk = c ^ (k&7)
template <int KDIM, int OUTD, bool G1>
__global__ void __launch_bounds__(256, 1)
gemm_h(const float* __restrict__ bias) {
    extern __shared__ char smraw[];
    uint32_t sb = smem_u32(smraw);
    int tid = threadIdx.x, lane = tid & 31, wid = tid >> 5;
    int e = blockIdx.z;
    int off = g_off[e], cnt = g_off[e + 1] - off;
    int m0 = blockIdx.y * BM;
    if (m0 >= cnt) return;
    int n0 = blockIdx.x * BN;
    const __half* W = (G1 ? g_w1h : g_w2h) + (size_t)e * KDIM * OUTD;
    const float* be = bias + (size_t)e * OUTD;

    int arow = tid & 127;
    int ac   = tid >> 7;
    int amr  = m0 + arow; if (amr >= cnt) amr = cnt - 1;
    const __half* aptr;
    if (G1) aptr = g_xh + (size_t)g_slot_tok[off + amr] * KDIM;
    else    aptr = g_h  + (size_t)(off + amr) * KDIM;
    uint32_t a_dst[4];
    int a_go[4];
#pragma unroll
    for (int i = 0; i < 4; i++) {
        int c = ac + 2 * i;
        a_dst[i] = sb + arow * 128 + ((uint32_t)(c ^ (arow & 7))) * 16;
        a_go[i]  = c * 8;
    }

    int bk = tid >> 2;
    int blo = tid & 3;
    const __half* bptr = W + (size_t)bk * OUTD + n0;
    uint32_t b_dst[8];
    int b_go[8];
#pragma unroll
    for (int j = 0; j < 8; j++) {
        int c = blo + 4 * j;
        b_dst[j] = sb + B_OFF + bk * 512 + ((uint32_t)(c ^ (bk & 7))) * 16;
        b_go[j]  = c * 8;
    }

    int warpM = wid & 1, warpN = wid >> 1;
    uint32_t aFb = sb + (warpM * 64 + (lane & 15)) * 128;
    int hi = lane >> 4;
    uint32_t bFb = sb + B_OFF + (lane & 15) * 512;
    uint32_t swz = lane & 7;

    float acc[4][8][4];
#pragma unroll
    for (int mi = 0; mi < 4; mi++)
#pragma unroll
        for (int ni = 0; ni < 8; ni++)
#pragma unroll
            for (int q = 0; q < 4; q++) acc[mi][ni][q] = 0.f;

    const int NC = KDIM / BK;

#pragma unroll
    for (int s = 0; s < NST - 1; s++) {
        uint32_t so = s * STAGE_BYTES;
        const __half* ap = aptr + (size_t)s * BK;
        const __half* bp = bptr + (size_t)s * BK * OUTD;
#pragma unroll
        for (int i = 0; i < 4; i++) cp16(a_dst[i] + so, ap + a_go[i]);
#pragma unroll
        for (int j = 0; j < 8; j++) cp16(b_dst[j] + so, bp + b_go[j]);
        CP_COMMIT();
    }

    uint32_t afr[2][4][4], bfr[2][4][4];

    for (int c = 0; c < NC; c++) {
        CP_WAIT1();
        __syncthreads();

        int nc = c + NST - 1;
        if (nc < NC) {
            uint32_t so = (nc % NST) * STAGE_BYTES;
            const __half* ap = aptr + (size_t)nc * BK;
            const __half* bp = bptr + (size_t)nc * BK * OUTD;
#pragma unroll
            for (int i = 0; i < 4; i++) cp16(a_dst[i] + so, ap + a_go[i]);
#pragma unroll
            for (int j = 0; j < 8; j++) cp16(b_dst[j] + so, bp + b_go[j]);
        }
        CP_COMMIT();

        uint32_t so = (c % NST) * STAGE_BYTES;

#pragma unroll
        for (int mi = 0; mi < 4; mi++)
            ldsm_x4(afr[0][mi], aFb + so + mi * 2048 +
                    ((uint32_t)((0 * 2 + hi) ^ swz)) * 16);
#pragma unroll
        for (int p = 0; p < 4; p++)
            ldsm_x4_t(bfr[0][p], bFb + so + 0 * 8192 +
                      ((uint32_t)((warpN * 8 + p * 2 + hi) ^ swz)) * 16);

#pragma unroll
        for (int ks = 0; ks < 4; ks++) {
            int cur = ks & 1, nxt = cur ^ 1;
            if (ks < 3) {
#pragma unroll
                for (int mi = 0; mi < 4; mi++)
                    ldsm_x4(afr[nxt][mi], aFb + so + mi * 2048 +
                            ((uint32_t)(((ks + 1) * 2 + hi) ^ swz)) * 16);
#pragma unroll
                for (int p = 0; p < 4; p++)
                    ldsm_x4_t(bfr[nxt][p], bFb + so + (ks + 1) * 8192 +
                              ((uint32_t)((warpN * 8 + p * 2 + hi) ^ swz)) * 16);
            }
#pragma unroll
            for (int mi = 0; mi < 4; mi++)
#pragma unroll
                for (int ni = 0; ni < 8; ni++)
                    mma_16816(acc[mi][ni], afr[cur][mi],
                              &bfr[cur][ni >> 1][(ni & 1) * 2]);
        }
    }

    int gid = lane >> 2, tig = lane & 3;
#pragma unroll
    for (int mi = 0; mi < 4; mi++) {
#pragma unroll
        for (int h2 = 0; h2 < 2; h2++) {
            int mrel = m0 + warpM * 64 + mi * 16 + gid + h2 * 8;
            if (mrel >= cnt) continue;
            size_t rowbase = (size_t)(off + mrel) * OUTD;
#pragma unroll
            for (int ni = 0; ni < 8; ni++) {
                int col = n0 + warpN * 64 + ni * 8 + 2 * tig;
                float v0 = acc[mi][ni][h2 * 2 + 0] + be[col];
                float v1 = acc[mi][ni][h2 * 2 + 1] + be[col + 1];
                if (G1) {
                    v0 = fmaxf(v0, 0.f);
                    v1 = fmaxf(v1, 0.f);
                    *(__half2*)(g_h + rowbase + col) = __floats2half2_rn(v0, v1);
                } else {
                    float2 v; v.x = v0; v.y = v1;
                    *(float2*)(g_y + rowbase + col) = v;
                }
            }
        }
    }
}

// ---------------- combine (float4, ILP 2) ------------------------------------
__global__ void combine_kernel(float* __restrict__ out) {
    int base = blockIdx.x * (blockDim.x * 2) + threadIdx.x;
#pragma unroll
    for (int u = 0; u < 2; u++) {
        int idx = base + u * blockDim.x;          // over T_TOK*DM/4
        if (idx >= T_TOK * DM / 4) continue;
        int t = idx >> 8, d4 = idx & 255;
        int s0 = g_tok_slot[2 * t], s1 = g_tok_slot[2 * t + 1];
        float w0 = g_tok_w[2 * t], w1 = g_tok_w[2 * t + 1];
        float4 a = ((const float4*)(g_y + (size_t)s0 * DM))[d4];
        float4 b = ((const float4*)(g_y + (size_t)s1 * DM))[d4];
        float4 r;
        r.x = w0 * a.x + w1 * b.x;
        r.y = w0 * a.y + w1 * b.y;
        r.z = w0 * a.z + w1 * b.z;
        r.w = w0 * a.w + w1 * b.w;
        ((float4*)out)[idx] = r;
    }
}

// -----------------------------------------------------------------------------
static cudaStream_t g_s1 = nullptr;
static cudaEvent_t  g_e0 = nullptr, g_e1 = nullptr, g_e2 = nullptr;

extern "C" void kernel_launch(void* const* d_in, const int* in_sizes, int n_in,
                              void* d_out, int out_size) {
    const float* x  = (const float*)d_in[0];
    const float* Wg = (const float*)d_in[1];
    const float* bg = (const float*)d_in[2];
    const float* W1 = (const float*)d_in[3];
    const float* b1 = (const float*)d_in[4];
    const float* W2 = (const float*)d_in[5];
    const float* b2 = (const float*)d_in[6];
    float* out = (float*)d_out;

    if (!g_s1) {
        cudaStreamCreateWithFlags(&g_s1, cudaStreamNonBlocking);
        cudaEventCreateWithFlags(&g_e0, cudaEventDisableTiming);
        cudaEventCreateWithFlags(&g_e1, cudaEventDisableTiming);
        cudaEventCreateWithFlags(&g_e2, cudaEventDisableTiming);
        cudaFuncSetAttribute(gemm_h<DM, DF, true>,
                             cudaFuncAttributeMaxDynamicSharedMemorySize, SMEM_DYN);
        cudaFuncSetAttribute(gemm_h<DF, DM, false>,
                             cudaFuncAttributeMaxDynamicSharedMemorySize, SMEM_DYN);
    }

    // fork side stream for weight conversion
    cudaEventRecord(g_e0, 0);
    cudaStreamWaitEvent(g_s1, g_e0, 0);
    cvt_w1x_kernel<<<(N4_W1 + N4_X + 511) / 512, 256, 0, g_s1>>>(W1, x);
    cudaEventRecord(g_e1, g_s1);
    cvt_w2_kernel<<<(N4_W2 + 511) / 512, 256, 0, g_s1>>>(W2);
    cudaEventRecord(g_e2, g_s1);

    // main stream: routing in parallel with converts
    gate_kernel<<<T_TOK / 16, 128>>>(x, Wg, bg);
    route_kernel<<<1, 1024>>>();

    cudaStreamWaitEvent(0, g_e1, 0);   // need W1 + x halves
    gemm_h<DM, DF, true><<<dim3(DF / BN, T_TOK / BM, NE), 256, SMEM_DYN>>>(b1);
    cudaStreamWaitEvent(0, g_e2, 0);   // need W2 half (joins side stream)
    gemm_h<DF, DM, false><<<dim3(DM / BN, T_TOK / BM, NE), 256, SMEM_DYN>>>(b2);
    combine_kernel<<<(T_TOK * DM / 4 + 511) / 512, 256>>>(out);
}